// round 11
// baseline (speedup 1.0000x reference)
#include <cuda_runtime.h>
#include <cuda_fp16.h>
#include <cstdint>

#define SLEN 2048
#define DDIM 128
#define NB 16
#define TQ 64
#define TK 64
#define THREADS 128

// strides in halves
#define QS 136
#define KS 136
#define VS 136

// smem offsets in halves: K double + V double only (Q lives in registers)
#define SK0_H 0
#define SK1_H 8704
#define SV0_H 17408
#define SV1_H 26112
#define SMEM_BYTES (34816 * 2)     // 69632 B -> 3 CTAs/SM

static __device__ __half g_Qh[(size_t)NB * SLEN * DDIM];
static __device__ __half g_Th[(size_t)NB * SLEN * DDIM];
static __device__ __half g_Vh[(size_t)NB * SLEN * DDIM];

__device__ __forceinline__ uint32_t smem_u32(const void* p) {
    uint32_t a;
    asm("{ .reg .u64 t; cvta.to.shared.u64 t, %1; cvt.u32.u64 %0, t; }" : "=r"(a) : "l"(p));
    return a;
}
__device__ __forceinline__ void cp16(uint32_t dst, const void* src) {
    asm volatile("cp.async.cg.shared.global [%0], [%1], 16;" :: "r"(dst), "l"(src) : "memory");
}
#define CP_COMMIT() asm volatile("cp.async.commit_group;" ::: "memory")
#define CP_WAIT0()  asm volatile("cp.async.wait_group 0;" ::: "memory")

__device__ __forceinline__ void ldsm4(uint32_t* r, uint32_t a) {
    asm volatile("ldmatrix.sync.aligned.m8n8.x4.shared.b16 {%0,%1,%2,%3}, [%4];"
                 : "=r"(r[0]), "=r"(r[1]), "=r"(r[2]), "=r"(r[3]) : "r"(a));
}
__device__ __forceinline__ void ldsm4t(uint32_t* r, uint32_t a) {
    asm volatile("ldmatrix.sync.aligned.m8n8.x4.trans.shared.b16 {%0,%1,%2,%3}, [%4];"
                 : "=r"(r[0]), "=r"(r[1]), "=r"(r[2]), "=r"(r[3]) : "r"(a));
}
__device__ __forceinline__ void mma16(float* d, uint32_t a0, uint32_t a1, uint32_t a2,
                                      uint32_t a3, uint32_t b0, uint32_t b1) {
    asm volatile("mma.sync.aligned.m16n8k16.row.col.f32.f16.f16.f32 "
                 "{%0,%1,%2,%3}, {%4,%5,%6,%7}, {%8,%9}, {%0,%1,%2,%3};"
                 : "+f"(d[0]), "+f"(d[1]), "+f"(d[2]), "+f"(d[3])
                 : "r"(a0), "r"(a1), "r"(a2), "r"(a3), "r"(b0), "r"(b1));
}
__device__ __forceinline__ uint32_t ex2h2(uint32_t u) {
    uint32_t r;
    asm("ex2.approx.f16x2 %0, %1;" : "=r"(r) : "r"(u));
    return r;
}

// ---------------- fused conversion pre-kernel (Q, T, V -> fp16) ----------------
__global__ void convAll(const float* __restrict__ Q, const float* __restrict__ T,
                        const float* __restrict__ V,
                        __half* __restrict__ Qh, __half* __restrict__ Th,
                        __half* __restrict__ Vh) {
    const float* s;
    __half* d;
    if (blockIdx.y == 0)      { s = Q; d = Qh; }
    else if (blockIdx.y == 1) { s = T; d = Th; }
    else                      { s = V; d = Vh; }
    int i = blockIdx.x * blockDim.x + threadIdx.x;    // i < n/8
    float4 v0 = ((const float4*)s)[2 * i + 0];
    float4 v1 = ((const float4*)s)[2 * i + 1];
    __half2 h0 = __floats2half2_rn(v0.x, v0.y);
    __half2 h1 = __floats2half2_rn(v0.z, v0.w);
    __half2 h2 = __floats2half2_rn(v1.x, v1.y);
    __half2 h3 = __floats2half2_rn(v1.z, v1.w);
    uint4 o = make_uint4(*(uint32_t*)&h0, *(uint32_t*)&h1,
                         *(uint32_t*)&h2, *(uint32_t*)&h3);
    ((uint4*)d)[i] = o;
}

// ---------------- main attention kernel ----------------
__global__ __launch_bounds__(THREADS, 3)
void attn_h(const __half* __restrict__ Qh, const __half* __restrict__ Th,
            const __half* __restrict__ Vh, float* __restrict__ Og) {
    extern __shared__ __align__(16) char smraw[];
    const uint32_t sb = smem_u32(smraw);

    const int idx = blockIdx.x;
    const int qt = (SLEN / TQ - 1) - (idx >> 4);   // LPT: heavy first
    const int b = idx & 15;

    const int tid = threadIdx.x;
    const int warp = tid >> 5, lane = tid & 31;
    const int lq = lane >> 2;
    const int lr = lane & 3;
    const int wr = warp * 16;
    const float CEX = 0.12751754f;                // log2(e)/sqrt(128)
    const float BIGN = -30000.0f;

    const int l15 = lane & 15;
    const int lc8 = (lane >> 4) << 3;

    // ldmatrix base addresses (bytes)
    uint32_t kb[2][4], vbb[2];
    #pragma unroll
    for (int bf = 0; bf < 2; bf++) {
        const int kh = bf ? SK1_H : SK0_H;
        const int vh = bf ? SV1_H : SV0_H;
        #pragma unroll
        for (int p = 0; p < 4; p++)
            kb[bf][p] = sb + 2 * (kh + (p * 16 + l15) * KS + lc8);
        vbb[bf] = sb + 2 * (vh + l15 * VS + lc8);
    }

    const __half* qg = Qh + ((size_t)b * SLEN + (size_t)qt * TQ) * DDIM;
    const __half* kgb = Th + (size_t)b * SLEN * DDIM;
    const __half* vgb = Vh + (size_t)b * SLEN * DDIM;

    // ---- prologue: Q (staged in SK1 buffer) + K0 + V0 ----
    #pragma unroll
    for (int it = 0; it < 8; it++) {
        int i = it * THREADS + tid;
        int r = i >> 4, c = i & 15;
        cp16(sb + 2 * (SK1_H + r * QS + c * 8), qg + (size_t)r * DDIM + c * 8);
        cp16(sb + 2 * (SK0_H + r * KS + c * 8), kgb + (size_t)r * DDIM + c * 8);
        cp16(sb + 2 * (SV0_H + r * VS + c * 8), vgb + (size_t)r * DDIM + c * 8);
    }
    CP_COMMIT();
    CP_WAIT0();
    __syncthreads();

    // Q fragments: register-resident for the whole kernel (32 regs)
    uint32_t QF[8][4];
    {
        const uint32_t qa = sb + 2 * (SK1_H + (wr + l15) * QS + lc8);
        #pragma unroll
        for (int ks = 0; ks < 8; ks++) ldsm4(QF[ks], qa + 32u * ks);
    }

    float Oa[16][4];
    #pragma unroll
    for (int nt = 0; nt < 16; nt++)
        #pragma unroll
        for (int k = 0; k < 4; k++) Oa[nt][k] = 0.0f;
    float rslo = 0.0f, rshi = 0.0f;

    const int nkt = qt + 1;
    for (int kt = 0; kt < nkt; kt++) {
        const int bf = kt & 1;
        CP_WAIT0();
        __syncthreads();    // K/V(kt) published; bf^1 buffers free (incl. Q staging at kt=0)

        // ---- prefetch kt+1 into alternate buffers ----
        if (kt + 1 < nkt) {
            const uint32_t skb = sb + 2 * ((bf ^ 1) ? SK1_H : SK0_H);
            const uint32_t svb = sb + 2 * ((bf ^ 1) ? SV1_H : SV0_H);
            const __half* kg = kgb + (size_t)(kt + 1) * TK * DDIM;
            const __half* vg = vgb + (size_t)(kt + 1) * TK * DDIM;
            #pragma unroll
            for (int it = 0; it < 8; it++) {
                int i = it * THREADS + tid;
                int r = i >> 4, c = i & 15;
                cp16(skb + 2 * (r * KS + c * 8), kg + (size_t)r * DDIM + c * 8);
                cp16(svb + 2 * (r * VS + c * 8), vg + (size_t)r * DDIM + c * 8);
            }
        }
        CP_COMMIT();

        // ---- QK^T (warp tile 16x64), A = persistent Q fragments ----
        float S[8][4];
        #pragma unroll
        for (int nt = 0; nt < 8; nt++)
            #pragma unroll
            for (int k = 0; k < 4; k++) S[nt][k] = 0.0f;

        #pragma unroll
        for (int ks = 0; ks < 8; ks++) {
            const uint32_t ko = 32u * ks;
            #pragma unroll
            for (int p = 0; p < 4; p++) {
                uint32_t B[4];
                ldsm4(B, kb[bf][p] + ko);
                mma16(S[2 * p + 0], QF[ks][0], QF[ks][1], QF[ks][2], QF[ks][3], B[0], B[2]);
                mma16(S[2 * p + 1], QF[ks][0], QF[ks][1], QF[ks][2], QF[ks][3], B[1], B[3]);
            }
        }

        // ---- epilogue: threshold + causal + f16x2 exp2 -> register P ----
        const bool diag = (kt == qt);
        const int grlo = qt * TQ + wr + lq;
        const int grhi = grlo + 8;
        uint32_t pl[8], ph[8];
        __half2 accLo = __float2half2_rn(0.0f);
        __half2 accHi = __float2half2_rn(0.0f);
        #pragma unroll
        for (int nt = 0; nt < 8; nt++) {
            const int c = nt * 8 + lr * 2;
            const int gc = kt * TK + c;
            float l0 = (S[nt][0] > 0.3f) ? S[nt][0] * CEX : 0.0f;
            float l1 = (S[nt][1] > 0.3f) ? S[nt][1] * CEX : 0.0f;
            float l2 = (S[nt][2] > 0.3f) ? S[nt][2] * CEX : 0.0f;
            float l3 = (S[nt][3] > 0.3f) ? S[nt][3] * CEX : 0.0f;
            if (diag) {
                if (gc     > grlo) l0 = BIGN;
                if (gc + 1 > grlo) l1 = BIGN;
                if (gc     > grhi) l2 = BIGN;
                if (gc + 1 > grhi) l3 = BIGN;
            }
            __half2 hlo = __floats2half2_rn(l0, l1);
            __half2 hhi = __floats2half2_rn(l2, l3);
            pl[nt] = ex2h2(*(uint32_t*)&hlo);
            ph[nt] = ex2h2(*(uint32_t*)&hhi);
            accLo = __hadd2(accLo, *(__half2*)&pl[nt]);
            accHi = __hadd2(accHi, *(__half2*)&ph[nt]);
        }
        {
            float2 fl = __half22float2(accLo);
            float2 fh = __half22float2(accHi);
            rslo += fl.x + fl.y;
            rshi += fh.x + fh.y;
        }

        // ---- PV: A = register P fragments, B = V via ldmatrix.trans ----
        #pragma unroll
        for (int ks = 0; ks < 4; ks++) {
            const uint32_t ko = 4352u * ks;   // 16 k-rows * 136 halves * 2B
            const uint32_t a0 = pl[2 * ks], a1 = ph[2 * ks];
            const uint32_t a2 = pl[2 * ks + 1], a3 = ph[2 * ks + 1];
            #pragma unroll
            for (int p = 0; p < 8; p++) {
                uint32_t B[4];
                ldsm4t(B, vbb[bf] + ko + 32u * p);
                mma16(Oa[2 * p + 0], a0, a1, a2, a3, B[0], B[1]);
                mma16(Oa[2 * p + 1], a0, a1, a2, a3, B[2], B[3]);
            }
        }
    }

    // ---- rowsum reduce within quad (warp-exclusive rows) ----
    rslo += __shfl_xor_sync(0xffffffffu, rslo, 1);
    rslo += __shfl_xor_sync(0xffffffffu, rslo, 2);
    rshi += __shfl_xor_sync(0xffffffffu, rshi, 1);
    rshi += __shfl_xor_sync(0xffffffffu, rshi, 2);
    const float invlo = 1.0f / rslo;
    const float invhi = 1.0f / rshi;

    // ---- normalize + store ----
    float* outb = Og + ((size_t)b * SLEN + (size_t)qt * TQ) * DDIM;
    const int rlo = wr + lq;
    const int rhi = rlo + 8;
    #pragma unroll
    for (int nt = 0; nt < 16; nt++) {
        const int c = nt * 8 + lr * 2;
        *(float2*)(outb + (size_t)rlo * DDIM + c) =
            make_float2(Oa[nt][0] * invlo, Oa[nt][1] * invlo);
        *(float2*)(outb + (size_t)rhi * DDIM + c) =
            make_float2(Oa[nt][2] * invhi, Oa[nt][3] * invhi);
    }
}

extern "C" void kernel_launch(void* const* d_in, const int* in_sizes, int n_in,
                              void* d_out, int out_size) {
    (void)in_sizes; (void)n_in; (void)out_size;
    const float* Q = (const float*)d_in[0];
    const float* T = (const float*)d_in[1];
    const float* V = (const float*)d_in[2];
    float* O = (float*)d_out;

    __half *qh, *th, *vh;
    cudaGetSymbolAddress((void**)&qh, g_Qh);
    cudaGetSymbolAddress((void**)&th, g_Th);
    cudaGetSymbolAddress((void**)&vh, g_Vh);

    const int n8 = NB * SLEN * DDIM / 8;
    dim3 cgrid(n8 / 256, 3);
    convAll<<<cgrid, 256>>>(Q, T, V, qh, th, vh);

    cudaFuncSetAttribute(attn_h, cudaFuncAttributeMaxDynamicSharedMemorySize, SMEM_BYTES);
    attn_h<<<(SLEN / TQ) * NB, THREADS, SMEM_BYTES>>>(qh, th, vh, O);
}

// round 13
// speedup vs baseline: 1.2900x; 1.2900x over previous
#include <cuda_runtime.h>
#include <cuda_fp16.h>
#include <cstdint>

#define SLEN 2048
#define DDIM 128
#define NB 16
#define TQ 64
#define TK 64
#define THREADS 128

// strides in halves
#define QS 136
#define KS 136
#define VS 136

// smem offsets in halves: K double + V double (Q lives in registers, staged via SK1)
#define SK0_H 0
#define SK1_H 8704
#define SV0_H 17408
#define SV1_H 26112
#define SMEM_BYTES (34816 * 2)     // 69632 B

static __device__ __half g_Qh[(size_t)NB * SLEN * DDIM];
static __device__ __half g_Th[(size_t)NB * SLEN * DDIM];
static __device__ __half g_Vh[(size_t)NB * SLEN * DDIM];

__device__ __forceinline__ uint32_t smem_u32(const void* p) {
    uint32_t a;
    asm("{ .reg .u64 t; cvta.to.shared.u64 t, %1; cvt.u32.u64 %0, t; }" : "=r"(a) : "l"(p));
    return a;
}
__device__ __forceinline__ void cp16(uint32_t dst, const void* src) {
    asm volatile("cp.async.cg.shared.global [%0], [%1], 16;" :: "r"(dst), "l"(src) : "memory");
}
#define CP_COMMIT() asm volatile("cp.async.commit_group;" ::: "memory")
#define CP_WAIT0()  asm volatile("cp.async.wait_group 0;" ::: "memory")

__device__ __forceinline__ void ldsm4(uint32_t* r, uint32_t a) {
    asm volatile("ldmatrix.sync.aligned.m8n8.x4.shared.b16 {%0,%1,%2,%3}, [%4];"
                 : "=r"(r[0]), "=r"(r[1]), "=r"(r[2]), "=r"(r[3]) : "r"(a));
}
__device__ __forceinline__ void ldsm4t(uint32_t* r, uint32_t a) {
    asm volatile("ldmatrix.sync.aligned.m8n8.x4.trans.shared.b16 {%0,%1,%2,%3}, [%4];"
                 : "=r"(r[0]), "=r"(r[1]), "=r"(r[2]), "=r"(r[3]) : "r"(a));
}
__device__ __forceinline__ void mma16(float* d, uint32_t a0, uint32_t a1, uint32_t a2,
                                      uint32_t a3, uint32_t b0, uint32_t b1) {
    asm volatile("mma.sync.aligned.m16n8k16.row.col.f32.f16.f16.f32 "
                 "{%0,%1,%2,%3}, {%4,%5,%6,%7}, {%8,%9}, {%0,%1,%2,%3};"
                 : "+f"(d[0]), "+f"(d[1]), "+f"(d[2]), "+f"(d[3])
                 : "r"(a0), "r"(a1), "r"(a2), "r"(a3), "r"(b0), "r"(b1));
}
__device__ __forceinline__ uint32_t ex2h2(uint32_t u) {
    uint32_t r;
    asm("ex2.approx.f16x2 %0, %1;" : "=r"(r) : "r"(u));
    return r;
}

// ---------------- fused conversion pre-kernel (Q, T, V -> fp16) ----------------
__global__ void convAll(const float* __restrict__ Q, const float* __restrict__ T,
                        const float* __restrict__ V,
                        __half* __restrict__ Qh, __half* __restrict__ Th,
                        __half* __restrict__ Vh) {
    const float* s;
    __half* d;
    if (blockIdx.y == 0)      { s = Q; d = Qh; }
    else if (blockIdx.y == 1) { s = T; d = Th; }
    else                      { s = V; d = Vh; }
    int i = blockIdx.x * blockDim.x + threadIdx.x;    // i < n/8
    float4 v0 = ((const float4*)s)[2 * i + 0];
    float4 v1 = ((const float4*)s)[2 * i + 1];
    __half2 h0 = __floats2half2_rn(v0.x, v0.y);
    __half2 h1 = __floats2half2_rn(v0.z, v0.w);
    __half2 h2 = __floats2half2_rn(v1.x, v1.y);
    __half2 h3 = __floats2half2_rn(v1.z, v1.w);
    uint4 o = make_uint4(*(uint32_t*)&h0, *(uint32_t*)&h1,
                         *(uint32_t*)&h2, *(uint32_t*)&h3);
    ((uint4*)d)[i] = o;
}

// ---------------- main attention kernel ----------------
__global__ __launch_bounds__(THREADS, 2)
void attn_h(const __half* __restrict__ Qh, const __half* __restrict__ Th,
            const __half* __restrict__ Vh, float* __restrict__ Og) {
    extern __shared__ __align__(16) char smraw[];
    const uint32_t sb = smem_u32(smraw);

    const int idx = blockIdx.x;
    const int qt = (SLEN / TQ - 1) - (idx >> 4);   // LPT: heavy first
    const int b = idx & 15;

    const int tid = threadIdx.x;
    const int warp = tid >> 5, lane = tid & 31;
    const int lq = lane >> 2;
    const int lr = lane & 3;
    const int wr = warp * 16;
    const float CEX = 0.12751754f;                // log2(e)/sqrt(128)
    const float BIGN = -30000.0f;

    const int l15 = lane & 15;
    const int lc8 = (lane >> 4) << 3;

    // ldmatrix base addresses (bytes)
    uint32_t kb[2][4], vbb[2];
    #pragma unroll
    for (int bf = 0; bf < 2; bf++) {
        const int kh = bf ? SK1_H : SK0_H;
        const int vh = bf ? SV1_H : SV0_H;
        #pragma unroll
        for (int p = 0; p < 4; p++)
            kb[bf][p] = sb + 2 * (kh + (p * 16 + l15) * KS + lc8);
        vbb[bf] = sb + 2 * (vh + l15 * VS + lc8);
    }

    const __half* qg = Qh + ((size_t)b * SLEN + (size_t)qt * TQ) * DDIM;
    const __half* kgb = Th + (size_t)b * SLEN * DDIM;
    const __half* vgb = Vh + (size_t)b * SLEN * DDIM;

    // ---- prologue: Q (staged in SK1) + K0 + V0 ----
    #pragma unroll
    for (int it = 0; it < 8; it++) {
        int i = it * THREADS + tid;
        int r = i >> 4, c = i & 15;
        cp16(sb + 2 * (SK1_H + r * QS + c * 8), qg + (size_t)r * DDIM + c * 8);
        cp16(sb + 2 * (SK0_H + r * KS + c * 8), kgb + (size_t)r * DDIM + c * 8);
        cp16(sb + 2 * (SV0_H + r * VS + c * 8), vgb + (size_t)r * DDIM + c * 8);
    }
    CP_COMMIT();
    CP_WAIT0();
    __syncthreads();

    // Q fragments: register-resident for the whole kernel (32 regs)
    uint32_t QF[8][4];
    {
        const uint32_t qa = sb + 2 * (SK1_H + (wr + l15) * QS + lc8);
        #pragma unroll
        for (int ks = 0; ks < 8; ks++) ldsm4(QF[ks], qa + 32u * ks);
    }

    float Oa[16][4];
    #pragma unroll
    for (int nt = 0; nt < 16; nt++)
        #pragma unroll
        for (int k = 0; k < 4; k++) Oa[nt][k] = 0.0f;
    float rslo = 0.0f, rshi = 0.0f;

    const int nkt = qt + 1;
    for (int kt = 0; kt < nkt; kt++) {
        const int bf = kt & 1;
        CP_WAIT0();
        __syncthreads();    // K/V(kt) published; bf^1 buffers free (QF read done @kt=0)

        // ---- prefetch K(kt+1) only (V deferred past QK to de-batch LSU) ----
        const bool more = (kt + 1 < nkt);
        const __half* kg = kgb + (size_t)(kt + 1) * TK * DDIM;
        const __half* vg = vgb + (size_t)(kt + 1) * TK * DDIM;
        const uint32_t skb = sb + 2 * ((bf ^ 1) ? SK1_H : SK0_H);
        const uint32_t svb = sb + 2 * ((bf ^ 1) ? SV1_H : SV0_H);
        if (more) {
            #pragma unroll
            for (int it = 0; it < 8; it++) {
                int i = it * THREADS + tid;
                int r = i >> 4, c = i & 15;
                cp16(skb + 2 * (r * KS + c * 8), kg + (size_t)r * DDIM + c * 8);
            }
        }

        // ---- QK^T (warp tile 16x64), A = persistent Q fragments ----
        float S[8][4];
        #pragma unroll
        for (int nt = 0; nt < 8; nt++)
            #pragma unroll
            for (int k = 0; k < 4; k++) S[nt][k] = 0.0f;

        #pragma unroll
        for (int ks = 0; ks < 8; ks++) {
            const uint32_t ko = 32u * ks;
            #pragma unroll
            for (int p = 0; p < 4; p++) {
                uint32_t B[4];
                ldsm4(B, kb[bf][p] + ko);
                mma16(S[2 * p + 0], QF[ks][0], QF[ks][1], QF[ks][2], QF[ks][3], B[0], B[2]);
                mma16(S[2 * p + 1], QF[ks][0], QF[ks][1], QF[ks][2], QF[ks][3], B[1], B[3]);
            }
        }

        // ---- prefetch V(kt+1); single commit covers K+V for this tile ----
        if (more) {
            #pragma unroll
            for (int it = 0; it < 8; it++) {
                int i = it * THREADS + tid;
                int r = i >> 4, c = i & 15;
                cp16(svb + 2 * (r * VS + c * 8), vg + (size_t)r * DDIM + c * 8);
            }
        }
        CP_COMMIT();

        // ---- interleaved epilogue + PV: per k-chunk, 2 P-fragments then 16 MMAs ----
        const bool diag = (kt == qt);
        const int grlo = qt * TQ + wr + lq;
        const int grhi = grlo + 8;
        __half2 accLo = __float2half2_rn(0.0f);
        __half2 accHi = __float2half2_rn(0.0f);

        #pragma unroll
        for (int ks = 0; ks < 4; ks++) {
            uint32_t pl2[2], ph2[2];
            #pragma unroll
            for (int half_ = 0; half_ < 2; half_++) {
                const int nt = 2 * ks + half_;
                const int c = nt * 8 + lr * 2;
                const int gc = kt * TK + c;
                float l0 = (S[nt][0] > 0.3f) ? S[nt][0] * CEX : 0.0f;
                float l1 = (S[nt][1] > 0.3f) ? S[nt][1] * CEX : 0.0f;
                float l2 = (S[nt][2] > 0.3f) ? S[nt][2] * CEX : 0.0f;
                float l3 = (S[nt][3] > 0.3f) ? S[nt][3] * CEX : 0.0f;
                if (diag) {
                    if (gc     > grlo) l0 = BIGN;
                    if (gc + 1 > grlo) l1 = BIGN;
                    if (gc     > grhi) l2 = BIGN;
                    if (gc + 1 > grhi) l3 = BIGN;
                }
                __half2 hlo = __floats2half2_rn(l0, l1);
                __half2 hhi = __floats2half2_rn(l2, l3);
                pl2[half_] = ex2h2(*(uint32_t*)&hlo);
                ph2[half_] = ex2h2(*(uint32_t*)&hhi);
                accLo = __hadd2(accLo, *(__half2*)&pl2[half_]);
                accHi = __hadd2(accHi, *(__half2*)&ph2[half_]);
            }
            const uint32_t ko = 4352u * ks;   // 16 k-rows * 136 halves * 2B
            #pragma unroll
            for (int p = 0; p < 8; p++) {
                uint32_t B[4];
                ldsm4t(B, vbb[bf] + ko + 32u * p);
                mma16(Oa[2 * p + 0], pl2[0], ph2[0], pl2[1], ph2[1], B[0], B[1]);
                mma16(Oa[2 * p + 1], pl2[0], ph2[0], pl2[1], ph2[1], B[2], B[3]);
            }
        }
        {
            float2 fl = __half22float2(accLo);
            float2 fh = __half22float2(accHi);
            rslo += fl.x + fl.y;
            rshi += fh.x + fh.y;
        }
    }

    // ---- rowsum reduce within quad (warp-exclusive rows) ----
    rslo += __shfl_xor_sync(0xffffffffu, rslo, 1);
    rslo += __shfl_xor_sync(0xffffffffu, rslo, 2);
    rshi += __shfl_xor_sync(0xffffffffu, rshi, 1);
    rshi += __shfl_xor_sync(0xffffffffu, rshi, 2);
    const float invlo = 1.0f / rslo;
    const float invhi = 1.0f / rshi;

    // ---- normalize + store ----
    float* outb = Og + ((size_t)b * SLEN + (size_t)qt * TQ) * DDIM;
    const int rlo = wr + lq;
    const int rhi = rlo + 8;
    #pragma unroll
    for (int nt = 0; nt < 16; nt++) {
        const int c = nt * 8 + lr * 2;
        *(float2*)(outb + (size_t)rlo * DDIM + c) =
            make_float2(Oa[nt][0] * invlo, Oa[nt][1] * invlo);
        *(float2*)(outb + (size_t)rhi * DDIM + c) =
            make_float2(Oa[nt][2] * invhi, Oa[nt][3] * invhi);
    }
}

extern "C" void kernel_launch(void* const* d_in, const int* in_sizes, int n_in,
                              void* d_out, int out_size) {
    (void)in_sizes; (void)n_in; (void)out_size;
    const float* Q = (const float*)d_in[0];
    const float* T = (const float*)d_in[1];
    const float* V = (const float*)d_in[2];
    float* O = (float*)d_out;

    __half *qh, *th, *vh;
    cudaGetSymbolAddress((void**)&qh, g_Qh);
    cudaGetSymbolAddress((void**)&th, g_Th);
    cudaGetSymbolAddress((void**)&vh, g_Vh);

    const int n8 = NB * SLEN * DDIM / 8;
    dim3 cgrid(n8 / 256, 3);
    convAll<<<cgrid, 256>>>(Q, T, V, qh, th, vh);

    cudaFuncSetAttribute(attn_h, cudaFuncAttributeMaxDynamicSharedMemorySize, SMEM_BYTES);
    attn_h<<<(SLEN / TQ) * NB, THREADS, SMEM_BYTES>>>(qh, th, vh, O);
}